// round 13
// baseline (speedup 1.0000x reference)
#include <cuda_runtime.h>
#include <cuda_fp16.h>
#include <cstdint>

// ---------------- problem constants (fixed by dataset) ----------------
#define M_TOTAL 4096      // B*S
#define K_DIM   768       // D
#define N_TOTAL 50257     // V

#define BM 128
#define BN 128
#define BK 64             // fp16: 64 elems = 128B row (SW128-style swizzle)
#define KC (K_DIM / BK)   // 12
#define STAGES 3
#define THREADS 256

#define STAGE_BYTES (BM * 128 + BN * 128)   // 32768
#define SMEM_REQ (STAGES * STAGE_BYTES)     // 98304  (2 CTAs/SM)

// Scratch: fp16 activations and fp16 W_out (static device arrays = sanctioned path)
__device__ __align__(1024) __half g_h[M_TOTAL * K_DIM];
__device__ __align__(1024) __half g_bh[(size_t)N_TOTAL * K_DIM];

// ---------------- PTX helpers (baseline sm_80-class PTX only) ----------------
__device__ __forceinline__ uint32_t smem_u32(const void* p) {
    uint32_t a;
    asm("{ .reg .u64 t; cvta.to.shared.u64 t, %1; cvt.u32.u64 %0, t; }" : "=r"(a) : "l"(p));
    return a;
}
__device__ __forceinline__ void cp16(uint32_t sdst, const void* gsrc) {
    asm volatile("cp.async.cg.shared.global [%0], [%1], 16;" :: "r"(sdst), "l"(gsrc));
}
__device__ __forceinline__ void ldsm_x4(uint32_t& r0, uint32_t& r1, uint32_t& r2, uint32_t& r3,
                                        uint32_t addr) {
    asm volatile("ldmatrix.sync.aligned.m8n8.x4.shared.b16 {%0,%1,%2,%3}, [%4];"
                 : "=r"(r0), "=r"(r1), "=r"(r2), "=r"(r3) : "r"(addr));
}
__device__ __forceinline__ void mma16816(float* c, const uint32_t* a, uint32_t b0, uint32_t b1) {
    asm volatile(
        "mma.sync.aligned.m16n8k16.row.col.f32.f16.f16.f32 "
        "{%0,%1,%2,%3}, {%4,%5,%6,%7}, {%8,%9}, {%0,%1,%2,%3};"
        : "+f"(c[0]), "+f"(c[1]), "+f"(c[2]), "+f"(c[3])
        : "r"(a[0]), "r"(a[1]), "r"(a[2]), "r"(a[3]), "r"(b0), "r"(b1));
}

// -------- kernel 1: fused prep: rmsnorm (blocks < M) + W cvt (rest) --------
__global__ void prep_kernel(const int* __restrict__ tok,
                            const float* __restrict__ emb,
                            const float* __restrict__ w,
                            const float4* __restrict__ wout,
                            int M, int D, int n4, int cvtBlocks) {
    if (blockIdx.x < (unsigned)M) {
        int row = blockIdx.x;
        int t = tok[row];
        const float* e = emb + (size_t)t * D;

        float ss = 0.f;
        for (int i = threadIdx.x; i < D; i += blockDim.x) {
            float v = e[i];
            ss += v * v;
        }
        __shared__ float red[8];
        #pragma unroll
        for (int o = 16; o > 0; o >>= 1) ss += __shfl_xor_sync(~0u, ss, o);
        if ((threadIdx.x & 31) == 0) red[threadIdx.x >> 5] = ss;
        __syncthreads();
        if (threadIdx.x < 8) {
            float v = red[threadIdx.x];
            #pragma unroll
            for (int o = 4; o > 0; o >>= 1) v += __shfl_xor_sync(0xffu, v, o);
            if (threadIdx.x == 0) red[0] = v;
        }
        __syncthreads();
        float scale = rsqrtf(red[0] / (float)D + 1e-5f);

        __half* out = g_h + (size_t)row * D;
        for (int i = threadIdx.x; i < D; i += blockDim.x) {
            out[i] = __float2half_rn(e[i] * scale * w[i]);
        }
    } else {
        int i = (blockIdx.x - M) * blockDim.x + threadIdx.x;
        int stride = cvtBlocks * blockDim.x;
        uint2* dst = reinterpret_cast<uint2*>(g_bh);
        for (; i < n4; i += stride) {
            float4 v = wout[i];
            __half2 h0 = __floats2half2_rn(v.x, v.y);
            __half2 h1 = __floats2half2_rn(v.z, v.w);
            uint2 o;
            o.x = *reinterpret_cast<uint32_t*>(&h0);
            o.y = *reinterpret_cast<uint32_t*>(&h1);
            dst[i] = o;
        }
    }
}

// ---------------- kernel 2: fp16 mma.sync GEMM ----------------
// C[M,N] = g_h[M,K] * g_bh[N,K]^T
// R3 loop structure (measured best) with two work-reducing edits:
//  - loads use pre-swizzled smem offsets (constant/thread) + incremented ptrs
//  - direct scalar post-loop epilogue (no smem transpose), __stcs streaming
__global__ void __launch_bounds__(THREADS, 2)
gemm_kernel(float* __restrict__ C) {
    extern __shared__ char smem[];
    const uint32_t sb = smem_u32(smem);

    const int tid  = threadIdx.x;
    const int lane = tid & 31;
    const int w    = tid >> 5;
    const int warp_m = w & 3;      // 4 warps over M: 32 rows each
    const int warp_n = w >> 2;     // 2 warps over N: 64 cols each
    const int g = lane >> 2;       // groupID
    const int t = lane & 3;        // threadID in group

    const int m0 = blockIdx.x * BM;     // m fast-varying -> B tiles L2-shared
    const int n0 = blockIdx.y * BN;

    // ---- load setup: swizzled smem offsets are kc-invariant; global ptrs increment ----
    const int rbase = tid >> 3;            // 0..31
    const int colb  = (tid & 7) * 16;      // byte col in 128B row

    uint32_t adst[4], bdst[4];             // swizzled offsets within a stage
    const char* aptr[4];
    const char* bptr[4];
    #pragma unroll
    for (int p = 0; p < 4; p++) {
        int r = rbase + p * 32;
        uint32_t off = (uint32_t)(r * 128 + colb);
        adst[p] = off ^ ((off >> 3) & 0x70);
        bdst[p] = adst[p] + BM * 128;
        aptr[p] = reinterpret_cast<const char*>(g_h) + (size_t)(m0 + r) * (K_DIM * 2) + colb;
        int rn = n0 + r; if (rn >= N_TOTAL) rn = N_TOTAL - 1;
        bptr[p] = reinterpret_cast<const char*>(g_bh) + (size_t)rn * (K_DIM * 2) + colb;
    }

    // sequential chunk loads: ptrs advance +128B per call
    auto load = [&](int s) {
        uint32_t base = sb + (uint32_t)s * STAGE_BYTES;
        #pragma unroll
        for (int p = 0; p < 4; p++) {
            cp16(base + adst[p], aptr[p]);
            aptr[p] += 128;
        }
        #pragma unroll
        for (int p = 0; p < 4; p++) {
            cp16(base + bdst[p], bptr[p]);
            bptr[p] += 128;
        }
        asm volatile("cp.async.commit_group;");
    };

    // ---- ldmatrix address precompute (row offset + swizzle xor mask) ----
    const int lrow  = lane & 15;
    const int lkoff = (lane >> 4) << 4;    // 0 or 16 bytes
    uint32_t rowA[2], mskA[2];
    #pragma unroll
    for (int mt = 0; mt < 2; mt++) {
        uint32_t off = (uint32_t)((warp_m * 32 + mt * 16 + lrow) * 128 + lkoff);
        rowA[mt] = off;
        mskA[mt] = (off >> 3) & 0x70;
    }
    uint32_t rowB[4], mskB[4];
    #pragma unroll
    for (int np = 0; np < 4; np++) {
        uint32_t off = (uint32_t)((warp_n * 64 + np * 16 + lrow) * 128 + lkoff);
        rowB[np] = off;
        mskB[np] = (off >> 3) & 0x70;
    }

    float acc[2][8][4];
    #pragma unroll
    for (int mt = 0; mt < 2; mt++)
        #pragma unroll
        for (int nt = 0; nt < 8; nt++)
            #pragma unroll
            for (int i = 0; i < 4; i++) acc[mt][nt][i] = 0.f;

    auto compute = [&](int s) {
        const uint32_t abase = sb + (uint32_t)s * STAGE_BYTES;
        const uint32_t bbase = abase + BM * 128;
        #pragma unroll
        for (int ks = 0; ks < 4; ks++) {
            const uint32_t kadd = (uint32_t)(ks * 32);
            uint32_t a[2][4];
            #pragma unroll
            for (int mt = 0; mt < 2; mt++)
                ldsm_x4(a[mt][0], a[mt][1], a[mt][2], a[mt][3],
                        abase + ((rowA[mt] + kadd) ^ mskA[mt]));
            #pragma unroll
            for (int np = 0; np < 4; np++) {
                uint32_t b0, b1, b2, b3;   // b0/b2: even 8-col tile (k lo/hi); b1/b3: odd
                ldsm_x4(b0, b1, b2, b3, bbase + ((rowB[np] + kadd) ^ mskB[np]));
                #pragma unroll
                for (int mt = 0; mt < 2; mt++) {
                    mma16816(acc[mt][2 * np],     a[mt], b0, b2);
                    mma16816(acc[mt][2 * np + 1], a[mt], b1, b3);
                }
            }
        }
    };

    // ---- 3-stage pipeline (R3-exact: wait, ONE sync, load lookahead, compute) ----
    load(0);
    load(1);
    for (int kc = 0; kc < KC; kc++) {
        if (kc < KC - 1) asm volatile("cp.async.wait_group 1;");
        else             asm volatile("cp.async.wait_group 0;");
        __syncthreads();
        if (kc + 2 < KC) load((kc + 2) % STAGES);
        compute(kc % STAGES);
    }

    // ---- epilogue: direct scalar streaming stores (no smem, no barrier) ----
    // N_TOTAL odd -> scalar 4B stores only; per (mt,nt) the 4 t-threads jointly
    // cover full 32B row segments, so sector traffic matches the coalesced path.
    #pragma unroll
    for (int mt = 0; mt < 2; mt++) {
        const int r0 = m0 + warp_m * 32 + mt * 16 + g;
        const size_t b0 = (size_t)r0 * N_TOTAL;
        const size_t b8 = b0 + 8 * (size_t)N_TOTAL;
        #pragma unroll
        for (int nt = 0; nt < 8; nt++) {
            const int col = n0 + warp_n * 64 + nt * 8 + t * 2;
            if (col + 1 < N_TOTAL) {
                __stcs(C + b0 + col,     acc[mt][nt][0]);
                __stcs(C + b0 + col + 1, acc[mt][nt][1]);
                __stcs(C + b8 + col,     acc[mt][nt][2]);
                __stcs(C + b8 + col + 1, acc[mt][nt][3]);
            } else if (col < N_TOTAL) {
                __stcs(C + b0 + col, acc[mt][nt][0]);
                __stcs(C + b8 + col, acc[mt][nt][2]);
            }
        }
    }
}

// ---------------------------------------------------------------------
extern "C" void kernel_launch(void* const* d_in, const int* in_sizes, int n_in,
                              void* d_out, int out_size) {
    const int*   tok  = (const int*)d_in[0];    // [M] int32 token ids
    const float* emb  = (const float*)d_in[1];  // [V,D]
    const float* wn   = (const float*)d_in[2];  // [D]
    const float* wout = (const float*)d_in[3];  // [V,D]
    float* out = (float*)d_out;

    int M = in_sizes[0];
    int D = in_sizes[2];
    int N = in_sizes[3] / D;

    // 1) fused: gather+RMSNorm->fp16  ||  W_out->fp16
    int n4 = (N * D) / 4;
    int cvtBlocks = 4096;
    prep_kernel<<<M + cvtBlocks, 256>>>(tok, emb, wn, (const float4*)wout,
                                        M, D, n4, cvtBlocks);

    // 2) fp16 mma.sync GEMM (m fast-varying: B tiles L2-shared)
    cudaFuncSetAttribute(gemm_kernel, cudaFuncAttributeMaxDynamicSharedMemorySize, SMEM_REQ);
    dim3 grid(M / BM, (N + BN - 1) / BN);
    gemm_kernel<<<grid, THREADS, SMEM_REQ>>>(out);
}

// round 14
// speedup vs baseline: 1.1834x; 1.1834x over previous
#include <cuda_runtime.h>
#include <cuda_fp16.h>
#include <cstdint>

// ---------------- problem constants (fixed by dataset) ----------------
#define M_TOTAL 4096      // B*S
#define K_DIM   768       // D
#define N_TOTAL 50257     // V

#define BM 128
#define BN 128
#define BK 64             // fp16: 64 elems = 128B row (SW128-style swizzle)
#define KC (K_DIM / BK)   // 12
#define STAGES 3
#define THREADS 256

#define STAGE_BYTES (BM * 128 + BN * 128)   // 32768
#define SMEM_REQ (STAGES * STAGE_BYTES)     // 98304  (2 CTAs/SM)

// Scratch: fp16 activations and fp16 W_out (static device arrays = sanctioned path)
__device__ __align__(1024) __half g_h[M_TOTAL * K_DIM];
__device__ __align__(1024) __half g_bh[(size_t)N_TOTAL * K_DIM];

// ---------------- PTX helpers (baseline sm_80-class PTX only) ----------------
__device__ __forceinline__ uint32_t smem_u32(const void* p) {
    uint32_t a;
    asm("{ .reg .u64 t; cvta.to.shared.u64 t, %1; cvt.u32.u64 %0, t; }" : "=r"(a) : "l"(p));
    return a;
}
__device__ __forceinline__ void cp16(uint32_t sdst, const void* gsrc) {
    asm volatile("cp.async.cg.shared.global [%0], [%1], 16;" :: "r"(sdst), "l"(gsrc));
}
__device__ __forceinline__ void ldsm_x4(uint32_t& r0, uint32_t& r1, uint32_t& r2, uint32_t& r3,
                                        uint32_t addr) {
    asm volatile("ldmatrix.sync.aligned.m8n8.x4.shared.b16 {%0,%1,%2,%3}, [%4];"
                 : "=r"(r0), "=r"(r1), "=r"(r2), "=r"(r3) : "r"(addr));
}
__device__ __forceinline__ void mma16816(float* c, const uint32_t* a, uint32_t b0, uint32_t b1) {
    asm volatile(
        "mma.sync.aligned.m16n8k16.row.col.f32.f16.f16.f32 "
        "{%0,%1,%2,%3}, {%4,%5,%6,%7}, {%8,%9}, {%0,%1,%2,%3};"
        : "+f"(c[0]), "+f"(c[1]), "+f"(c[2]), "+f"(c[3])
        : "r"(a[0]), "r"(a[1]), "r"(a[2]), "r"(a[3]), "r"(b0), "r"(b1));
}

// -------- kernel 1: fused prep: rmsnorm (blocks < M) + W cvt (rest) --------
__global__ void prep_kernel(const int* __restrict__ tok,
                            const float* __restrict__ emb,
                            const float* __restrict__ w,
                            const float4* __restrict__ wout,
                            int M, int D, int n4, int cvtBlocks) {
    if (blockIdx.x < (unsigned)M) {
        int row = blockIdx.x;
        int t = tok[row];
        const float* e = emb + (size_t)t * D;

        float ss = 0.f;
        for (int i = threadIdx.x; i < D; i += blockDim.x) {
            float v = e[i];
            ss += v * v;
        }
        __shared__ float red[8];
        #pragma unroll
        for (int o = 16; o > 0; o >>= 1) ss += __shfl_xor_sync(~0u, ss, o);
        if ((threadIdx.x & 31) == 0) red[threadIdx.x >> 5] = ss;
        __syncthreads();
        if (threadIdx.x < 8) {
            float v = red[threadIdx.x];
            #pragma unroll
            for (int o = 4; o > 0; o >>= 1) v += __shfl_xor_sync(0xffu, v, o);
            if (threadIdx.x == 0) red[0] = v;
        }
        __syncthreads();
        float scale = rsqrtf(red[0] / (float)D + 1e-5f);

        __half* out = g_h + (size_t)row * D;
        for (int i = threadIdx.x; i < D; i += blockDim.x) {
            out[i] = __float2half_rn(e[i] * scale * w[i]);
        }
    } else {
        int i = (blockIdx.x - M) * blockDim.x + threadIdx.x;
        int stride = cvtBlocks * blockDim.x;
        uint2* dst = reinterpret_cast<uint2*>(g_bh);
        for (; i < n4; i += stride) {
            float4 v = wout[i];
            __half2 h0 = __floats2half2_rn(v.x, v.y);
            __half2 h1 = __floats2half2_rn(v.z, v.w);
            uint2 o;
            o.x = *reinterpret_cast<uint32_t*>(&h0);
            o.y = *reinterpret_cast<uint32_t*>(&h1);
            dst[i] = o;
        }
    }
}

// ---------------- kernel 2: fp16 mma.sync GEMM ----------------
// C[M,N] = g_h[M,K] * g_bh[N,K]^T
// R12 loop (measured best, 834us) + R13's validated pointer-increment loads.
// Epilogue: smem transpose -> coalesced STG (scalar direct stores measured
// +150us via 4x L2 wavefronts; do not revisit).
__global__ void __launch_bounds__(THREADS, 2)
gemm_kernel(float* __restrict__ C) {
    extern __shared__ char smem[];
    const uint32_t sb = smem_u32(smem);

    const int tid  = threadIdx.x;
    const int lane = tid & 31;
    const int w    = tid >> 5;
    const int warp_m = w & 3;      // 4 warps over M: 32 rows each
    const int warp_n = w >> 2;     // 2 warps over N: 64 cols each
    const int g = lane >> 2;       // groupID
    const int t = lane & 3;        // threadID in group

    const int m0 = blockIdx.x * BM;     // m fast-varying -> B tiles L2-shared
    const int n0 = blockIdx.y * BN;

    // ---- load setup: swizzled smem offsets are kc-invariant; global ptrs increment ----
    const int rbase = tid >> 3;            // 0..31
    const int colb  = (tid & 7) * 16;      // byte col in 128B row

    uint32_t adst[4], bdst[4];             // swizzled offsets within a stage
    const char* aptr[4];
    const char* bptr[4];
    #pragma unroll
    for (int p = 0; p < 4; p++) {
        int r = rbase + p * 32;
        uint32_t off = (uint32_t)(r * 128 + colb);
        adst[p] = off ^ ((off >> 3) & 0x70);
        bdst[p] = adst[p] + BM * 128;
        aptr[p] = reinterpret_cast<const char*>(g_h) + (size_t)(m0 + r) * (K_DIM * 2) + colb;
        int rn = n0 + r; if (rn >= N_TOTAL) rn = N_TOTAL - 1;
        bptr[p] = reinterpret_cast<const char*>(g_bh) + (size_t)rn * (K_DIM * 2) + colb;
    }

    // sequential chunk loads: ptrs advance +128B per call
    auto load = [&](int s) {
        uint32_t base = sb + (uint32_t)s * STAGE_BYTES;
        #pragma unroll
        for (int p = 0; p < 4; p++) {
            cp16(base + adst[p], aptr[p]);
            aptr[p] += 128;
        }
        #pragma unroll
        for (int p = 0; p < 4; p++) {
            cp16(base + bdst[p], bptr[p]);
            bptr[p] += 128;
        }
        asm volatile("cp.async.commit_group;");
    };

    // ---- ldmatrix address precompute (row offset + swizzle xor mask) ----
    const int lrow  = lane & 15;
    const int lkoff = (lane >> 4) << 4;    // 0 or 16 bytes
    uint32_t rowA[2], mskA[2];
    #pragma unroll
    for (int mt = 0; mt < 2; mt++) {
        uint32_t off = (uint32_t)((warp_m * 32 + mt * 16 + lrow) * 128 + lkoff);
        rowA[mt] = off;
        mskA[mt] = (off >> 3) & 0x70;
    }
    uint32_t rowB[4], mskB[4];
    #pragma unroll
    for (int np = 0; np < 4; np++) {
        uint32_t off = (uint32_t)((warp_n * 64 + np * 16 + lrow) * 128 + lkoff);
        rowB[np] = off;
        mskB[np] = (off >> 3) & 0x70;
    }

    float acc[2][8][4];
    #pragma unroll
    for (int mt = 0; mt < 2; mt++)
        #pragma unroll
        for (int nt = 0; nt < 8; nt++)
            #pragma unroll
            for (int i = 0; i < 4; i++) acc[mt][nt][i] = 0.f;

    auto compute = [&](int s) {
        const uint32_t abase = sb + (uint32_t)s * STAGE_BYTES;
        const uint32_t bbase = abase + BM * 128;
        #pragma unroll
        for (int ks = 0; ks < 4; ks++) {
            const uint32_t kadd = (uint32_t)(ks * 32);
            uint32_t a[2][4];
            #pragma unroll
            for (int mt = 0; mt < 2; mt++)
                ldsm_x4(a[mt][0], a[mt][1], a[mt][2], a[mt][3],
                        abase + ((rowA[mt] + kadd) ^ mskA[mt]));
            #pragma unroll
            for (int np = 0; np < 4; np++) {
                uint32_t b0, b1, b2, b3;   // b0/b2: even 8-col tile (k lo/hi); b1/b3: odd
                ldsm_x4(b0, b1, b2, b3, bbase + ((rowB[np] + kadd) ^ mskB[np]));
                #pragma unroll
                for (int mt = 0; mt < 2; mt++) {
                    mma16816(acc[mt][2 * np],     a[mt], b0, b2);
                    mma16816(acc[mt][2 * np + 1], a[mt], b1, b3);
                }
            }
        }
    };

    // ---- 3-stage pipeline (R3-exact: wait, ONE sync, load lookahead, compute) ----
    load(0);
    load(1);
    for (int kc = 0; kc < KC; kc++) {
        if (kc < KC - 1) asm volatile("cp.async.wait_group 1;");
        else             asm volatile("cp.async.wait_group 0;");
        __syncthreads();
        if (kc + 2 < KC) load((kc + 2) % STAGES);
        compute(kc % STAGES);
    }
    __syncthreads();   // protect smem reuse by epilogue

    // ---- epilogue: frags -> padded smem -> coalesced STG ----
    // per-warp buffer: 32 rows x 68 floats (272B row, pad kills bank conflicts)
    const uint32_t buf = sb + (uint32_t)w * (32 * 272);
    #pragma unroll
    for (int mt = 0; mt < 2; mt++) {
        #pragma unroll
        for (int nt = 0; nt < 8; nt++) {
            uint32_t ad = buf + (uint32_t)((mt * 16 + g) * 272 + (nt * 8 + 2 * t) * 4);
            asm volatile("st.shared.v2.f32 [%0], {%1,%2};"
                         :: "r"(ad), "f"(acc[mt][nt][0]), "f"(acc[mt][nt][1]) : "memory");
            asm volatile("st.shared.v2.f32 [%0], {%1,%2};"
                         :: "r"(ad + 8 * 272), "f"(acc[mt][nt][2]), "f"(acc[mt][nt][3]) : "memory");
        }
    }
    __syncwarp();

    const int gcol0 = n0 + warp_n * 64;
    #pragma unroll 4
    for (int r = 0; r < 32; r++) {
        size_t rb = (size_t)(m0 + warp_m * 32 + r) * N_TOTAL;
        #pragma unroll
        for (int p = 0; p < 2; p++) {
            int cl = p * 32 + lane;
            int col = gcol0 + cl;
            float v;
            asm volatile("ld.shared.f32 %0, [%1];"
                         : "=f"(v) : "r"(buf + (uint32_t)(r * 272 + cl * 4)));
            if (col < N_TOTAL) C[rb + col] = v;
        }
    }
}

// ---------------------------------------------------------------------
extern "C" void kernel_launch(void* const* d_in, const int* in_sizes, int n_in,
                              void* d_out, int out_size) {
    const int*   tok  = (const int*)d_in[0];    // [M] int32 token ids
    const float* emb  = (const float*)d_in[1];  // [V,D]
    const float* wn   = (const float*)d_in[2];  // [D]
    const float* wout = (const float*)d_in[3];  // [V,D]
    float* out = (float*)d_out;

    int M = in_sizes[0];
    int D = in_sizes[2];
    int N = in_sizes[3] / D;

    // 1) fused: gather+RMSNorm->fp16  ||  W_out->fp16
    int n4 = (N * D) / 4;
    int cvtBlocks = 4096;
    prep_kernel<<<M + cvtBlocks, 256>>>(tok, emb, wn, (const float4*)wout,
                                        M, D, n4, cvtBlocks);

    // 2) fp16 mma.sync GEMM (m fast-varying: B tiles L2-shared)
    cudaFuncSetAttribute(gemm_kernel, cudaFuncAttributeMaxDynamicSharedMemorySize, SMEM_REQ);
    dim3 grid(M / BM, (N + BN - 1) / BN);
    gemm_kernel<<<grid, THREADS, SMEM_REQ>>>(out);
}

// round 15
// speedup vs baseline: 1.1888x; 1.0046x over previous
#include <cuda_runtime.h>
#include <cuda_fp16.h>
#include <cstdint>

// ---------------- problem constants (fixed by dataset) ----------------
#define M_TOTAL 4096      // B*S
#define K_DIM   768       // D
#define N_TOTAL 50257     // V

#define BM 128
#define BN 128
#define BK 64             // fp16: 64 elems = 128B row (SW128-style swizzle)
#define KC (K_DIM / BK)   // 12
#define STAGES 3
#define THREADS 256

#define STAGE_BYTES (BM * 128 + BN * 128)   // 32768
#define SMEM_REQ (STAGES * STAGE_BYTES)     // 98304  (2 CTAs/SM)

// Scratch: fp16 activations and fp16 W_out (static device arrays = sanctioned path)
__device__ __align__(1024) __half g_h[M_TOTAL * K_DIM];
__device__ __align__(1024) __half g_bh[(size_t)N_TOTAL * K_DIM];

// ---------------- PTX helpers (baseline sm_80-class PTX only) ----------------
__device__ __forceinline__ uint32_t smem_u32(const void* p) {
    uint32_t a;
    asm("{ .reg .u64 t; cvta.to.shared.u64 t, %1; cvt.u32.u64 %0, t; }" : "=r"(a) : "l"(p));
    return a;
}
__device__ __forceinline__ void cp16(uint32_t sdst, const void* gsrc) {
    asm volatile("cp.async.cg.shared.global [%0], [%1], 16;" :: "r"(sdst), "l"(gsrc));
}
__device__ __forceinline__ void ldsm_x4(uint32_t& r0, uint32_t& r1, uint32_t& r2, uint32_t& r3,
                                        uint32_t addr) {
    asm volatile("ldmatrix.sync.aligned.m8n8.x4.shared.b16 {%0,%1,%2,%3}, [%4];"
                 : "=r"(r0), "=r"(r1), "=r"(r2), "=r"(r3) : "r"(addr));
}
__device__ __forceinline__ void mma16816(float* c, const uint32_t* a, uint32_t b0, uint32_t b1) {
    asm volatile(
        "mma.sync.aligned.m16n8k16.row.col.f32.f16.f16.f32 "
        "{%0,%1,%2,%3}, {%4,%5,%6,%7}, {%8,%9}, {%0,%1,%2,%3};"
        : "+f"(c[0]), "+f"(c[1]), "+f"(c[2]), "+f"(c[3])
        : "r"(a[0]), "r"(a[1]), "r"(a[2]), "r"(a[3]), "r"(b0), "r"(b1));
}

// -------- kernel 1: fused prep: W cvt (low blockIdx, long pole) + rmsnorm --------
__global__ void prep_kernel(const int* __restrict__ tok,
                            const float* __restrict__ emb,
                            const float* __restrict__ w,
                            const float4* __restrict__ wout,
                            int M, int D, int n4, int cvtBlocks) {
    if (blockIdx.x < (unsigned)cvtBlocks) {
        // ---- W_out fp32 -> fp16 (grid-stride) — dispatched FIRST ----
        int i = blockIdx.x * blockDim.x + threadIdx.x;
        int stride = cvtBlocks * blockDim.x;
        uint2* dst = reinterpret_cast<uint2*>(g_bh);
        for (; i < n4; i += stride) {
            float4 v = wout[i];
            __half2 h0 = __floats2half2_rn(v.x, v.y);
            __half2 h1 = __floats2half2_rn(v.z, v.w);
            uint2 o;
            o.x = *reinterpret_cast<uint32_t*>(&h0);
            o.y = *reinterpret_cast<uint32_t*>(&h1);
            dst[i] = o;
        }
    } else {
        // ---- RMSNorm row (vectorized: 192 threads x float4 over D=768) ----
        int row = blockIdx.x - cvtBlocks;
        int t = tok[row];
        const float4* e4 = reinterpret_cast<const float4*>(emb + (size_t)t * D);
        const float4* w4 = reinterpret_cast<const float4*>(w);
        const int nv = D / 4;   // 192

        float4 v = make_float4(0.f, 0.f, 0.f, 0.f);
        float ss = 0.f;
        if (threadIdx.x < (unsigned)nv) {
            v = e4[threadIdx.x];
            ss = v.x * v.x + v.y * v.y + v.z * v.z + v.w * v.w;
        }
        __shared__ float red[8];
        #pragma unroll
        for (int o = 16; o > 0; o >>= 1) ss += __shfl_xor_sync(~0u, ss, o);
        if ((threadIdx.x & 31) == 0) red[threadIdx.x >> 5] = ss;
        __syncthreads();
        if (threadIdx.x < 8) {
            float s = red[threadIdx.x];
            #pragma unroll
            for (int o = 4; o > 0; o >>= 1) s += __shfl_xor_sync(0xffu, s, o);
            if (threadIdx.x == 0) red[0] = s;
        }
        __syncthreads();
        float scale = rsqrtf(red[0] / (float)D + 1e-5f);

        if (threadIdx.x < (unsigned)nv) {
            float4 ww = w4[threadIdx.x];
            __half2 h0 = __floats2half2_rn(v.x * scale * ww.x, v.y * scale * ww.y);
            __half2 h1 = __floats2half2_rn(v.z * scale * ww.z, v.w * scale * ww.w);
            uint2 o;
            o.x = *reinterpret_cast<uint32_t*>(&h0);
            o.y = *reinterpret_cast<uint32_t*>(&h1);
            reinterpret_cast<uint2*>(g_h + (size_t)row * D)[threadIdx.x] = o;
        }
    }
}

// ---------------- kernel 2: fp16 mma.sync GEMM (R14 byte-identical: 835.9us) ----------------
// C[M,N] = g_h[M,K] * g_bh[N,K]^T
__global__ void __launch_bounds__(THREADS, 2)
gemm_kernel(float* __restrict__ C) {
    extern __shared__ char smem[];
    const uint32_t sb = smem_u32(smem);

    const int tid  = threadIdx.x;
    const int lane = tid & 31;
    const int w    = tid >> 5;
    const int warp_m = w & 3;      // 4 warps over M: 32 rows each
    const int warp_n = w >> 2;     // 2 warps over N: 64 cols each
    const int g = lane >> 2;       // groupID
    const int t = lane & 3;        // threadID in group

    const int m0 = blockIdx.x * BM;     // m fast-varying -> B tiles L2-shared
    const int n0 = blockIdx.y * BN;

    // ---- load setup: swizzled smem offsets are kc-invariant; global ptrs increment ----
    const int rbase = tid >> 3;            // 0..31
    const int colb  = (tid & 7) * 16;      // byte col in 128B row

    uint32_t adst[4], bdst[4];             // swizzled offsets within a stage
    const char* aptr[4];
    const char* bptr[4];
    #pragma unroll
    for (int p = 0; p < 4; p++) {
        int r = rbase + p * 32;
        uint32_t off = (uint32_t)(r * 128 + colb);
        adst[p] = off ^ ((off >> 3) & 0x70);
        bdst[p] = adst[p] + BM * 128;
        aptr[p] = reinterpret_cast<const char*>(g_h) + (size_t)(m0 + r) * (K_DIM * 2) + colb;
        int rn = n0 + r; if (rn >= N_TOTAL) rn = N_TOTAL - 1;
        bptr[p] = reinterpret_cast<const char*>(g_bh) + (size_t)rn * (K_DIM * 2) + colb;
    }

    // sequential chunk loads: ptrs advance +128B per call
    auto load = [&](int s) {
        uint32_t base = sb + (uint32_t)s * STAGE_BYTES;
        #pragma unroll
        for (int p = 0; p < 4; p++) {
            cp16(base + adst[p], aptr[p]);
            aptr[p] += 128;
        }
        #pragma unroll
        for (int p = 0; p < 4; p++) {
            cp16(base + bdst[p], bptr[p]);
            bptr[p] += 128;
        }
        asm volatile("cp.async.commit_group;");
    };

    // ---- ldmatrix address precompute (row offset + swizzle xor mask) ----
    const int lrow  = lane & 15;
    const int lkoff = (lane >> 4) << 4;    // 0 or 16 bytes
    uint32_t rowA[2], mskA[2];
    #pragma unroll
    for (int mt = 0; mt < 2; mt++) {
        uint32_t off = (uint32_t)((warp_m * 32 + mt * 16 + lrow) * 128 + lkoff);
        rowA[mt] = off;
        mskA[mt] = (off >> 3) & 0x70;
    }
    uint32_t rowB[4], mskB[4];
    #pragma unroll
    for (int np = 0; np < 4; np++) {
        uint32_t off = (uint32_t)((warp_n * 64 + np * 16 + lrow) * 128 + lkoff);
        rowB[np] = off;
        mskB[np] = (off >> 3) & 0x70;
    }

    float acc[2][8][4];
    #pragma unroll
    for (int mt = 0; mt < 2; mt++)
        #pragma unroll
        for (int nt = 0; nt < 8; nt++)
            #pragma unroll
            for (int i = 0; i < 4; i++) acc[mt][nt][i] = 0.f;

    auto compute = [&](int s) {
        const uint32_t abase = sb + (uint32_t)s * STAGE_BYTES;
        const uint32_t bbase = abase + BM * 128;
        #pragma unroll
        for (int ks = 0; ks < 4; ks++) {
            const uint32_t kadd = (uint32_t)(ks * 32);
            uint32_t a[2][4];
            #pragma unroll
            for (int mt = 0; mt < 2; mt++)
                ldsm_x4(a[mt][0], a[mt][1], a[mt][2], a[mt][3],
                        abase + ((rowA[mt] + kadd) ^ mskA[mt]));
            #pragma unroll
            for (int np = 0; np < 4; np++) {
                uint32_t b0, b1, b2, b3;   // b0/b2: even 8-col tile (k lo/hi); b1/b3: odd
                ldsm_x4(b0, b1, b2, b3, bbase + ((rowB[np] + kadd) ^ mskB[np]));
                #pragma unroll
                for (int mt = 0; mt < 2; mt++) {
                    mma16816(acc[mt][2 * np],     a[mt], b0, b2);
                    mma16816(acc[mt][2 * np + 1], a[mt], b1, b3);
                }
            }
        }
    };

    // ---- 3-stage pipeline (wait, ONE sync, load lookahead, compute) ----
    load(0);
    load(1);
    for (int kc = 0; kc < KC; kc++) {
        if (kc < KC - 1) asm volatile("cp.async.wait_group 1;");
        else             asm volatile("cp.async.wait_group 0;");
        __syncthreads();
        if (kc + 2 < KC) load((kc + 2) % STAGES);
        compute(kc % STAGES);
    }
    __syncthreads();   // protect smem reuse by epilogue

    // ---- epilogue: frags -> padded smem -> coalesced STG ----
    // per-warp buffer: 32 rows x 68 floats (272B row, pad kills bank conflicts)
    const uint32_t buf = sb + (uint32_t)w * (32 * 272);
    #pragma unroll
    for (int mt = 0; mt < 2; mt++) {
        #pragma unroll
        for (int nt = 0; nt < 8; nt++) {
            uint32_t ad = buf + (uint32_t)((mt * 16 + g) * 272 + (nt * 8 + 2 * t) * 4);
            asm volatile("st.shared.v2.f32 [%0], {%1,%2};"
                         :: "r"(ad), "f"(acc[mt][nt][0]), "f"(acc[mt][nt][1]) : "memory");
            asm volatile("st.shared.v2.f32 [%0], {%1,%2};"
                         :: "r"(ad + 8 * 272), "f"(acc[mt][nt][2]), "f"(acc[mt][nt][3]) : "memory");
        }
    }
    __syncwarp();

    const int gcol0 = n0 + warp_n * 64;
    #pragma unroll 4
    for (int r = 0; r < 32; r++) {
        size_t rb = (size_t)(m0 + warp_m * 32 + r) * N_TOTAL;
        #pragma unroll
        for (int p = 0; p < 2; p++) {
            int cl = p * 32 + lane;
            int col = gcol0 + cl;
            float v;
            asm volatile("ld.shared.f32 %0, [%1];"
                         : "=f"(v) : "r"(buf + (uint32_t)(r * 272 + cl * 4)));
            if (col < N_TOTAL) C[rb + col] = v;
        }
    }
}

// ---------------------------------------------------------------------
extern "C" void kernel_launch(void* const* d_in, const int* in_sizes, int n_in,
                              void* d_out, int out_size) {
    const int*   tok  = (const int*)d_in[0];    // [M] int32 token ids
    const float* emb  = (const float*)d_in[1];  // [V,D]
    const float* wn   = (const float*)d_in[2];  // [D]
    const float* wout = (const float*)d_in[3];  // [V,D]
    float* out = (float*)d_out;

    int M = in_sizes[0];
    int D = in_sizes[2];
    int N = in_sizes[3] / D;

    // 1) fused prep: W_out->fp16 (first, long pole) || gather+RMSNorm->fp16
    int n4 = (N * D) / 4;
    int cvtBlocks = 4096;
    prep_kernel<<<cvtBlocks + M, 256>>>(tok, emb, wn, (const float4*)wout,
                                        M, D, n4, cvtBlocks);

    // 2) fp16 mma.sync GEMM (m fast-varying: B tiles L2-shared)
    cudaFuncSetAttribute(gemm_kernel, cudaFuncAttributeMaxDynamicSharedMemorySize, SMEM_REQ);
    dim3 grid(M / BM, (N + BN - 1) / BN);
    gemm_kernel<<<grid, THREADS, SMEM_REQ>>>(out);
}